// round 1
// baseline (speedup 1.0000x reference)
#include <cuda_runtime.h>
#include <math.h>

// ---------------- problem constants ----------------
#define B_N   4096
#define D1    200      // embedding dim
#define WIN   400      // 2*D1
#define WOUT  392      // WIN - FW + 1
#define OC    32
#define FW    9
#define T_N   288      // OC*FW  (fc1 output length)
#define FCL   12544    // OC*WOUT
#define EPSf  1e-5f

#define NGROUP 8       // m-split groups for wEff partials
#define MPERG  50      // 400 / 8

// ---------------- scratch (__device__ globals, no allocs) ----------------
__device__ float g_v[WIN];                 // fc2_w * s2
__device__ float g_consts[8];              // [0]=Cb+Cz, [1]=a0, [2]=c0, [3]=Ctot, [4]=bias
__device__ float g_wEffP[NGROUP][FCL];     // partial wEff sums
__device__ float g_A[WIN * T_N];           // banded weight matrix for Pb GEMM
__device__ float g_W1T[D1 * T_N];          // fc1_w transposed [d][t]
__device__ float g_kb[B_N * T_N];
__device__ float g_Pb[B_N * T_N];

// ---------------- K1: scalar/vector prep ----------------
__global__ void k_prep(const float* __restrict__ fc2_w, const float* __restrict__ fc2_b,
                       const float* __restrict__ bn2_g, const float* __restrict__ bn2_b,
                       const float* __restrict__ bn2_m, const float* __restrict__ bn2_v,
                       const float* __restrict__ fc_b,
                       const float* __restrict__ bn0_g, const float* __restrict__ bn0_b,
                       const float* __restrict__ bn0_m, const float* __restrict__ bn0_v,
                       const float* __restrict__ bias)
{
    __shared__ float red[512];
    int tid = threadIdx.x;
    float local = 0.f;
    if (tid < WIN) {
        float s2 = bn2_g[tid] * rsqrtf(bn2_v[tid] + EPSf);
        float v  = fc2_w[tid] * s2;
        g_v[tid] = v;
        // Cz part: fc2_w*(beta2 - mean2*s2);  Cb part: v*fc_b
        local = fc2_w[tid] * (bn2_b[tid] - bn2_m[tid] * s2) + v * fc_b[tid];
    }
    red[tid] = local;
    __syncthreads();
    for (int s = 256; s > 0; s >>= 1) {
        if (tid < s) red[tid] += red[tid + s];
        __syncthreads();
    }
    if (tid == 0) {
        g_consts[0] = red[0] + fc2_b[0];
        float a0 = bn0_g[0] * rsqrtf(bn0_v[0] + EPSf);
        g_consts[1] = a0;
        g_consts[2] = bn0_b[0] - bn0_m[0] * a0;
        g_consts[4] = bias[0];
    }
}

// ---------------- K2: wEff partials = sum_m v[m] * fc_w[m, f] ----------------
__global__ __launch_bounds__(256) void k_weff(const float* __restrict__ fc_w)
{
    int f4 = blockIdx.x * 256 + threadIdx.x;   // float4 index within FCL
    if (f4 >= FCL / 4) return;
    int g = blockIdx.y;
    int m0 = g * MPERG;
    const float4* src = reinterpret_cast<const float4*>(fc_w) + f4;
    float4 acc = make_float4(0.f, 0.f, 0.f, 0.f);
#pragma unroll 5
    for (int m = m0; m < m0 + MPERG; m++) {
        float vm = g_v[m];
        float4 w = src[(size_t)m * (FCL / 4)];
        acc.x = fmaf(vm, w.x, acc.x);
        acc.y = fmaf(vm, w.y, acc.y);
        acc.z = fmaf(vm, w.z, acc.z);
        acc.w = fmaf(vm, w.w, acc.w);
    }
    *reinterpret_cast<float4*>(&g_wEffP[g][f4 * 4]) = acc;
}

// ---------------- K3c: transpose fc1_w [288,200] -> W1T [200,288] ----------------
__global__ void k_transpose(const float* __restrict__ fc1_w)
{
    int idx = blockIdx.x * 256 + threadIdx.x;
    if (idx >= D1 * T_N) return;
    int d = idx / T_N, t = idx % T_N;
    g_W1T[idx] = fc1_w[t * D1 + d];
}

// ---------------- K3: build banded A[w', t=(o,j)] = s1[o]*wEff[o*392 + w'-j] ----------------
__global__ void k_buildA(const float* __restrict__ bn1_g, const float* __restrict__ bn1_v)
{
    int q = blockIdx.x * 256 + threadIdx.x;
    if (q >= (WIN * T_N) / 4) return;
    int base = q * 4;
    int wp = base / T_N;     // 288 % 4 == 0 -> all 4 elems share wp
    int t0 = base % T_N;
    float4 out;
    float* outp = &out.x;
#pragma unroll
    for (int i = 0; i < 4; i++) {
        int t = t0 + i;
        int o = t / FW, j = t % FW;
        int w = wp - j;
        float val = 0.f;
        if ((unsigned)w < (unsigned)WOUT) {
            float s1 = bn1_g[o] * rsqrtf(bn1_v[o] + EPSf);
            int idx = o * WOUT + w;
            float s = 0.f;
#pragma unroll
            for (int gg = 0; gg < NGROUP; gg++) s += g_wEffP[gg][idx];
            val = s1 * s;
        }
        outp[i] = val;
    }
    *reinterpret_cast<float4*>(&g_A[base]) = out;
}

// ---------------- K3b: Ck = sum_f t1[o(f)] * wEff[f];  Ctot = Ck + (Cb+Cz) ----------------
__global__ void k_ck(const float* __restrict__ bn1_g, const float* __restrict__ bn1_b,
                     const float* __restrict__ bn1_m, const float* __restrict__ bn1_v)
{
    __shared__ float red[256];
    int tid = threadIdx.x;
    float local = 0.f;
    for (int i = tid; i < FCL; i += 256) {
        int o = i / WOUT;
        float s1 = bn1_g[o] * rsqrtf(bn1_v[o] + EPSf);
        float t1 = bn1_b[o] - bn1_m[o] * s1;
        float s = 0.f;
#pragma unroll
        for (int gg = 0; gg < NGROUP; gg++) s += g_wEffP[gg][i];
        local += t1 * s;
    }
    red[tid] = local;
    __syncthreads();
    for (int s = 128; s > 0; s >>= 1) {
        if (tid < s) red[tid] += red[tid + s];
        __syncthreads();
    }
    if (tid == 0) g_consts[3] = red[0] + g_consts[0];
}

// ---------------- K4: kb[4096,288] = gather(R_table, r_idx) @ W1T + fc1_b ----------------
#define KC 8
__global__ __launch_bounds__(256) void k_kb(const int* __restrict__ r_idx,
                                            const float* __restrict__ R,
                                            const float* __restrict__ fc1_b)
{
    __shared__ float Rs[KC][64];
    __shared__ float Ws[KC][96];
    __shared__ int ridx[64];
    int tid = threadIdx.x;
    int m0 = blockIdx.y * 64, n0 = blockIdx.x * 96;
    if (tid < 64) ridx[tid] = r_idx[m0 + tid];
    __syncthreads();

    int ty = tid >> 4, tx = tid & 15;
    int row0 = ty * 4, col0 = tx * 6;
    int sr_row = tid >> 2, sr_d = (tid & 3) * 2;
    int sw_kk = (tid * 3) / 96, sw_t = (tid * 3) % 96;

    float acc[4][6] = {};
    for (int d0 = 0; d0 < D1; d0 += KC) {
        float2 rv = *reinterpret_cast<const float2*>(R + (size_t)ridx[sr_row] * D1 + d0 + sr_d);
        const float* wsrc = g_W1T + (size_t)(d0 + sw_kk) * T_N + n0 + sw_t;
        float w0 = wsrc[0], w1 = wsrc[1], w2 = wsrc[2];
        Rs[sr_d][sr_row] = rv.x;
        Rs[sr_d + 1][sr_row] = rv.y;
        Ws[sw_kk][sw_t] = w0; Ws[sw_kk][sw_t + 1] = w1; Ws[sw_kk][sw_t + 2] = w2;
        __syncthreads();
#pragma unroll
        for (int kk = 0; kk < KC; kk++) {
            float4 xr = *reinterpret_cast<const float4*>(&Rs[kk][row0]);
            float2 wa = *reinterpret_cast<const float2*>(&Ws[kk][col0]);
            float2 wb = *reinterpret_cast<const float2*>(&Ws[kk][col0 + 2]);
            float2 wc = *reinterpret_cast<const float2*>(&Ws[kk][col0 + 4]);
            float xv[4] = {xr.x, xr.y, xr.z, xr.w};
            float wv[6] = {wa.x, wa.y, wb.x, wb.y, wc.x, wc.y};
#pragma unroll
            for (int i = 0; i < 4; i++)
#pragma unroll
                for (int j = 0; j < 6; j++)
                    acc[i][j] = fmaf(xv[i], wv[j], acc[i][j]);
        }
        __syncthreads();
    }
#pragma unroll
    for (int i = 0; i < 4; i++) {
        float* dst = g_kb + (size_t)(m0 + row0 + i) * T_N + n0 + col0;
#pragma unroll
        for (int j = 0; j < 6; j++) dst[j] = acc[i][j] + fc1_b[n0 + col0 + j];
    }
}

// ---------------- K5: Pb[4096,288] = X @ A, X gathered from E_table (+bn0 affine) ----------------
__global__ __launch_bounds__(256) void k_pb(const int* __restrict__ e1_idx,
                                            const int* __restrict__ e2_idx,
                                            const float* __restrict__ E)
{
    __shared__ float Xs[KC][64];
    __shared__ float Ws[KC][96];
    __shared__ int idx1[64], idx2[64];
    int tid = threadIdx.x;
    int m0 = blockIdx.y * 64, n0 = blockIdx.x * 96;
    if (tid < 64) { idx1[tid] = e1_idx[m0 + tid]; idx2[tid] = e2_idx[m0 + tid]; }
    float a0 = g_consts[1], c0 = g_consts[2];
    __syncthreads();

    int ty = tid >> 4, tx = tid & 15;
    int row0 = ty * 4, col0 = tx * 6;
    int sr_row = tid >> 2, sr_d = (tid & 3) * 2;
    int sw_kk = (tid * 3) / 96, sw_t = (tid * 3) % 96;

    float acc[4][6] = {};
    for (int d0 = 0; d0 < WIN; d0 += KC) {
        int wp = d0 + sr_d;   // 200 % 8 == 0: both elems of the float2 on same side
        const float* src;
        if (wp < D1) src = E + (size_t)idx1[sr_row] * D1 + wp;
        else         src = E + (size_t)idx2[sr_row] * D1 + (wp - D1);
        float2 xv2 = *reinterpret_cast<const float2*>(src);
        const float* wsrc = g_A + (size_t)(d0 + sw_kk) * T_N + n0 + sw_t;
        float w0 = wsrc[0], w1 = wsrc[1], w2 = wsrc[2];
        Xs[sr_d][sr_row] = fmaf(a0, xv2.x, c0);
        Xs[sr_d + 1][sr_row] = fmaf(a0, xv2.y, c0);
        Ws[sw_kk][sw_t] = w0; Ws[sw_kk][sw_t + 1] = w1; Ws[sw_kk][sw_t + 2] = w2;
        __syncthreads();
#pragma unroll
        for (int kk = 0; kk < KC; kk++) {
            float4 xr = *reinterpret_cast<const float4*>(&Xs[kk][row0]);
            float2 wa = *reinterpret_cast<const float2*>(&Ws[kk][col0]);
            float2 wb = *reinterpret_cast<const float2*>(&Ws[kk][col0 + 2]);
            float2 wc = *reinterpret_cast<const float2*>(&Ws[kk][col0 + 4]);
            float xv[4] = {xr.x, xr.y, xr.z, xr.w};
            float wv[6] = {wa.x, wa.y, wb.x, wb.y, wc.x, wc.y};
#pragma unroll
            for (int i = 0; i < 4; i++)
#pragma unroll
                for (int j = 0; j < 6; j++)
                    acc[i][j] = fmaf(xv[i], wv[j], acc[i][j]);
        }
        __syncthreads();
    }
#pragma unroll
    for (int i = 0; i < 4; i++) {
        float* dst = g_Pb + (size_t)(m0 + row0 + i) * T_N + n0 + col0;
#pragma unroll
        for (int j = 0; j < 6; j++) dst[j] = acc[i][j];
    }
}

// ---------------- K6: out[b] = tanh( kb[b]·Pb[b] + Ctot ) + bias ----------------
__global__ void k_final(float* __restrict__ out)
{
    int b = blockIdx.x * 8 + (threadIdx.x >> 5);
    int lane = threadIdx.x & 31;
    const float* kb = g_kb + (size_t)b * T_N;
    const float* pb = g_Pb + (size_t)b * T_N;
    float acc = 0.f;
#pragma unroll
    for (int i = 0; i < 9; i++) {
        int t = lane + i * 32;
        acc = fmaf(kb[t], pb[t], acc);
    }
#pragma unroll
    for (int off = 16; off > 0; off >>= 1)
        acc += __shfl_xor_sync(0xFFFFFFFFu, acc, off);
    if (lane == 0) out[b] = tanhf(acc + g_consts[3]) + g_consts[4];
}

// ---------------- launch ----------------
extern "C" void kernel_launch(void* const* d_in, const int* in_sizes, int n_in,
                              void* d_out, int out_size)
{
    const int*   e1   = (const int*)d_in[0];
    const int*   ridx = (const int*)d_in[1];
    const int*   e2   = (const int*)d_in[2];
    const float* E    = (const float*)d_in[3];
    const float* R    = (const float*)d_in[4];
    const float* bn0g = (const float*)d_in[5];
    const float* bn0b = (const float*)d_in[6];
    const float* bn0m = (const float*)d_in[7];
    const float* bn0v = (const float*)d_in[8];
    const float* fc1w = (const float*)d_in[9];
    const float* fc1b = (const float*)d_in[10];
    const float* bn1g = (const float*)d_in[11];
    const float* bn1b = (const float*)d_in[12];
    const float* bn1m = (const float*)d_in[13];
    const float* bn1v = (const float*)d_in[14];
    const float* fcw  = (const float*)d_in[15];
    const float* fcb  = (const float*)d_in[16];
    const float* bn2g = (const float*)d_in[17];
    const float* bn2b = (const float*)d_in[18];
    const float* bn2m = (const float*)d_in[19];
    const float* bn2v = (const float*)d_in[20];
    const float* fc2w = (const float*)d_in[21];
    const float* fc2b = (const float*)d_in[22];
    const float* bias = (const float*)d_in[23];
    float* out = (float*)d_out;

    k_prep<<<1, 512>>>(fc2w, fc2b, bn2g, bn2b, bn2m, bn2v, fcb,
                       bn0g, bn0b, bn0m, bn0v, bias);
    k_weff<<<dim3((FCL / 4 + 255) / 256, NGROUP), 256>>>(fcw);
    k_transpose<<<(D1 * T_N + 255) / 256, 256>>>(fc1w);
    k_buildA<<<((WIN * T_N) / 4 + 255) / 256, 256>>>(bn1g, bn1v);
    k_ck<<<1, 256>>>(bn1g, bn1b, bn1m, bn1v);
    k_kb<<<dim3(3, B_N / 64), 256>>>(ridx, R, fc1b);
    k_pb<<<dim3(3, B_N / 64), 256>>>(e1, e2, E);
    k_final<<<B_N / 8, 256>>>(out);
}

// round 3
// speedup vs baseline: 1.5937x; 1.5937x over previous
#include <cuda_runtime.h>
#include <math.h>

// ---------------- problem constants ----------------
#define B_N   4096
#define D1    200
#define WIN   400
#define WOUT  392
#define OC    32
#define FW    9
#define T_N   288
#define FCL   12544
#define EPSf  1e-5f

#define NGROUP 8
#define MPERG  50

// ---------------- scratch (__device__ globals) ----------------
__device__ float g_v[WIN];                 // fc2_w * s2
__device__ float g_consts[8];              // [0]=Cb+Cz, [1]=a0, [2]=c0, [3]=Ctot, [4]=bias
__device__ float g_wEffP[NGROUP][FCL];     // partial wEff sums
__device__ float g_wEffS[FCL];             // s1[o] * wEff  (pre-scaled, reduced)
__device__ float g_ckp[49];                // Ck per-block partials
__device__ float g_W1T[D1 * T_N];          // fc1_w transposed [d][t]
__device__ float g_part[9 * B_N];          // dot-product partials per col-block

// ---------------- K1: scalar/vector prep ----------------
__global__ void k_prep(const float* __restrict__ fc2_w, const float* __restrict__ fc2_b,
                       const float* __restrict__ bn2_g, const float* __restrict__ bn2_b,
                       const float* __restrict__ bn2_m, const float* __restrict__ bn2_v,
                       const float* __restrict__ fc_b,
                       const float* __restrict__ bn0_g, const float* __restrict__ bn0_b,
                       const float* __restrict__ bn0_m, const float* __restrict__ bn0_v,
                       const float* __restrict__ bias)
{
    __shared__ float red[512];
    int tid = threadIdx.x;
    float local = 0.f;
    if (tid < WIN) {
        float s2 = bn2_g[tid] * rsqrtf(bn2_v[tid] + EPSf);
        float v  = fc2_w[tid] * s2;
        g_v[tid] = v;
        local = fc2_w[tid] * (bn2_b[tid] - bn2_m[tid] * s2) + v * fc_b[tid];
    }
    red[tid] = local;
    __syncthreads();
    for (int s = 256; s > 0; s >>= 1) {
        if (tid < s) red[tid] += red[tid + s];
        __syncthreads();
    }
    if (tid == 0) {
        g_consts[0] = red[0] + fc2_b[0];
        float a0 = bn0_g[0] * rsqrtf(bn0_v[0] + EPSf);
        g_consts[1] = a0;
        g_consts[2] = bn0_b[0] - bn0_m[0] * a0;
        g_consts[4] = bias[0];
    }
}

// ---------------- K2: wEff partials + fc1_w transpose (fused) ----------------
__global__ __launch_bounds__(256) void k_weff_trans(const float* __restrict__ fc_w,
                                                    const float* __restrict__ fc1_w)
{
    int bid = blockIdx.x;
    int tid = threadIdx.x;
    if (bid < 104) {
        // wEff partials: group g sums rows [g*50, g*50+50) of fc_w weighted by g_v
        int g = bid / 13, fb = bid % 13;
        __shared__ float vs[MPERG];
        if (tid < MPERG) vs[tid] = g_v[g * MPERG + tid];
        __syncthreads();
        int f4 = fb * 256 + tid;
        if (f4 >= FCL / 4) return;
        const float4* src = reinterpret_cast<const float4*>(fc_w)
                          + (size_t)g * MPERG * (FCL / 4) + f4;
        float4 acc = make_float4(0.f, 0.f, 0.f, 0.f);
#pragma unroll 5
        for (int m = 0; m < MPERG; m++) {
            float vm = vs[m];
            float4 w = src[(size_t)m * (FCL / 4)];
            acc.x = fmaf(vm, w.x, acc.x);
            acc.y = fmaf(vm, w.y, acc.y);
            acc.z = fmaf(vm, w.z, acc.z);
            acc.w = fmaf(vm, w.w, acc.w);
        }
        *reinterpret_cast<float4*>(&g_wEffP[g][f4 * 4]) = acc;
    } else {
        // transpose fc1_w [288,200] -> g_W1T [200,288]
        int idx = (bid - 104) * 256 + tid;
        if (idx < D1 * T_N) {
            int d = idx / T_N, t = idx % T_N;
            g_W1T[idx] = fc1_w[t * D1 + d];
        }
    }
}

// ---------------- K3: reduce partials -> wEffS (scaled by s1) + Ck partials ----------------
__global__ __launch_bounds__(256) void k_reduce(const float* __restrict__ bn1_g,
                                                const float* __restrict__ bn1_b,
                                                const float* __restrict__ bn1_m,
                                                const float* __restrict__ bn1_v)
{
    __shared__ float red[256];
    int tid = threadIdx.x;
    int f = blockIdx.x * 256 + tid;        // grid=49 -> exactly FCL
    int o = f / WOUT;
    float s1 = bn1_g[o] * rsqrtf(bn1_v[o] + EPSf);
    float t1 = bn1_b[o] - bn1_m[o] * s1;
    float s = 0.f;
#pragma unroll
    for (int g = 0; g < NGROUP; g++) s += g_wEffP[g][f];
    g_wEffS[f] = s1 * s;
    red[tid] = t1 * s;
    __syncthreads();
    for (int st = 128; st > 0; st >>= 1) {
        if (tid < st) red[tid] += red[tid + st];
        __syncthreads();
    }
    if (tid == 0) g_ckp[blockIdx.x] = red[0];
}

// ---------------- K4: Ctot = sum(ckp) + (Cb+Cz) ----------------
__global__ void k_ctot()
{
    __shared__ float sm[2];
    int t = threadIdx.x;  // 64
    float v = (t < 49) ? g_ckp[t] : 0.f;
#pragma unroll
    for (int off = 16; off > 0; off >>= 1) v += __shfl_xor_sync(0xFFFFFFFFu, v, off);
    if ((t & 31) == 0) sm[t >> 5] = v;
    __syncthreads();
    if (t == 0) g_consts[3] = sm[0] + sm[1] + g_consts[0];
}

// ---------------- K5: fused dual-GEMM + dot partials ----------------
// Block = 32 rows x 32 cols. 64 threads, thread tile 4x4.
// Phase 1: kb = gather(R) @ W1T            (k = 200)
// Phase 2: pb = bn0(gather(E)) @ A          (k = 400, A gathered on the fly)
// Then:    part[colblk][row] = sum_cols (kb + fc1_b) * pb
__global__ __launch_bounds__(64) void k_fused(const int* __restrict__ r_idx,
                                              const int* __restrict__ e1_idx,
                                              const int* __restrict__ e2_idx,
                                              const float* __restrict__ R,
                                              const float* __restrict__ E,
                                              const float* __restrict__ fc1_b)
{
    __shared__ float Xs[32][9];     // [row][kk] padded
    __shared__ float Ws[8][32];     // [kk][col]
    __shared__ int s_r[32], s_e1[32], s_e2[32];

    int tid = threadIdx.x;
    int n0 = blockIdx.x * 32, m0 = blockIdx.y * 32;
    if (tid < 32) {
        s_r[tid]  = r_idx[m0 + tid];
        s_e1[tid] = e1_idx[m0 + tid];
        s_e2[tid] = e2_idx[m0 + tid];
    }
    float a0 = g_consts[1], c0 = g_consts[2];

    int ty = tid >> 3, tx = tid & 7;          // compute mapping: rows=ty*4.., cols=tx*4..
    int xr = tid >> 1, xd = (tid & 1) * 4;    // X staging: row, k-offset
    int wk = tid >> 3, wc = (tid & 7) * 4;    // W staging: kk, col

    // phase-2 gather params (constant per thread)
    int o_[4], j_[4];
#pragma unroll
    for (int q = 0; q < 4; q++) {
        int t = n0 + wc + q;
        o_[q] = t / FW;
        j_[q] = t % FW;
    }
    __syncthreads();   // indices visible

    float rxv[4], rwv[4];
    // prologue: phase-1 chunk 0
    {
        float4 v4 = *reinterpret_cast<const float4*>(R + (size_t)s_r[xr] * D1 + xd);
        rxv[0] = v4.x; rxv[1] = v4.y; rxv[2] = v4.z; rxv[3] = v4.w;
        float4 w4 = *reinterpret_cast<const float4*>(g_W1T + (size_t)wk * T_N + n0 + wc);
        rwv[0] = w4.x; rwv[1] = w4.y; rwv[2] = w4.z; rwv[3] = w4.w;
    }

    float kb[4][4] = {}, pb[4][4] = {};

    // ---- phase 1: k = 200 (25 chunks of 8) ----
    for (int c = 0; c < 25; c++) {
        __syncthreads();
#pragma unroll
        for (int q = 0; q < 4; q++) Xs[xr][xd + q] = rxv[q];
        *reinterpret_cast<float4*>(&Ws[wk][wc]) = make_float4(rwv[0], rwv[1], rwv[2], rwv[3]);
        __syncthreads();
        if (c + 1 < 25) {
            int d0 = (c + 1) * 8;
            float4 v4 = *reinterpret_cast<const float4*>(R + (size_t)s_r[xr] * D1 + d0 + xd);
            rxv[0] = v4.x; rxv[1] = v4.y; rxv[2] = v4.z; rxv[3] = v4.w;
            float4 w4 = *reinterpret_cast<const float4*>(g_W1T + (size_t)(d0 + wk) * T_N + n0 + wc);
            rwv[0] = w4.x; rwv[1] = w4.y; rwv[2] = w4.z; rwv[3] = w4.w;
        } else {
            // prefetch phase-2 chunk 0 (wp = xd < 200 -> e1 side)
            float4 v4 = *reinterpret_cast<const float4*>(E + (size_t)s_e1[xr] * D1 + xd);
            rxv[0] = v4.x; rxv[1] = v4.y; rxv[2] = v4.z; rxv[3] = v4.w;
#pragma unroll
            for (int q = 0; q < 4; q++) {
                int w = wk - j_[q];
                rwv[q] = ((unsigned)w < (unsigned)WOUT) ? g_wEffS[o_[q] * WOUT + w] : 0.f;
            }
        }
#pragma unroll
        for (int kk = 0; kk < 8; kk++) {
            float xv[4];
#pragma unroll
            for (int i = 0; i < 4; i++) xv[i] = Xs[ty * 4 + i][kk];
            float4 wv4 = *reinterpret_cast<const float4*>(&Ws[kk][tx * 4]);
            float wv[4] = {wv4.x, wv4.y, wv4.z, wv4.w};
#pragma unroll
            for (int i = 0; i < 4; i++)
#pragma unroll
                for (int j = 0; j < 4; j++)
                    kb[i][j] = fmaf(xv[i], wv[j], kb[i][j]);
        }
    }

    // ---- phase 2: k = 400 (50 chunks of 8); bn0 affine applied at store ----
    for (int c = 0; c < 50; c++) {
        __syncthreads();
#pragma unroll
        for (int q = 0; q < 4; q++) Xs[xr][xd + q] = fmaf(a0, rxv[q], c0);
        *reinterpret_cast<float4*>(&Ws[wk][wc]) = make_float4(rwv[0], rwv[1], rwv[2], rwv[3]);
        __syncthreads();
        if (c + 1 < 50) {
            int d0 = (c + 1) * 8;
            int wp = d0 + xd;     // all 4 elems same side (D1 % 8 == 0)
            const float* base = (wp < D1) ? (E + (size_t)s_e1[xr] * D1 + wp)
                                          : (E + (size_t)s_e2[xr] * D1 + (wp - D1));
            float4 v4 = *reinterpret_cast<const float4*>(base);
            rxv[0] = v4.x; rxv[1] = v4.y; rxv[2] = v4.z; rxv[3] = v4.w;
#pragma unroll
            for (int q = 0; q < 4; q++) {
                int w = d0 + wk - j_[q];
                rwv[q] = ((unsigned)w < (unsigned)WOUT) ? g_wEffS[o_[q] * WOUT + w] : 0.f;
            }
        }
#pragma unroll
        for (int kk = 0; kk < 8; kk++) {
            float xv[4];
#pragma unroll
            for (int i = 0; i < 4; i++) xv[i] = Xs[ty * 4 + i][kk];
            float4 wv4 = *reinterpret_cast<const float4*>(&Ws[kk][tx * 4]);
            float wv[4] = {wv4.x, wv4.y, wv4.z, wv4.w};
#pragma unroll
            for (int i = 0; i < 4; i++)
#pragma unroll
                for (int j = 0; j < 4; j++)
                    pb[i][j] = fmaf(xv[i], wv[j], pb[i][j]);
        }
    }

    // ---- dot partials + reduce over cols ----
    float4 b4 = *reinterpret_cast<const float4*>(fc1_b + n0 + tx * 4);
    float bv[4] = {b4.x, b4.y, b4.z, b4.w};
    float pr[4];
#pragma unroll
    for (int i = 0; i < 4; i++) {
        float s = 0.f;
#pragma unroll
        for (int j = 0; j < 4; j++)
            s = fmaf(kb[i][j] + bv[j], pb[i][j], s);
        pr[i] = s;
    }
#pragma unroll
    for (int off = 1; off < 8; off <<= 1)
#pragma unroll
        for (int i = 0; i < 4; i++)
            pr[i] += __shfl_xor_sync(0xFFFFFFFFu, pr[i], off);
    if (tx == 0) {
#pragma unroll
        for (int i = 0; i < 4; i++)
            g_part[blockIdx.x * B_N + m0 + ty * 4 + i] = pr[i];
    }
}

// ---------------- K6: out[b] = tanh(sum parts + Ctot) + bias ----------------
__global__ void k_out(float* __restrict__ out)
{
    int b = blockIdx.x * 256 + threadIdx.x;
    float s = 0.f;
#pragma unroll
    for (int c = 0; c < 9; c++) s += g_part[c * B_N + b];
    out[b] = tanhf(s + g_consts[3]) + g_consts[4];
}

// ---------------- launch ----------------
extern "C" void kernel_launch(void* const* d_in, const int* in_sizes, int n_in,
                              void* d_out, int out_size)
{
    const int*   e1   = (const int*)d_in[0];
    const int*   ridx = (const int*)d_in[1];
    const int*   e2   = (const int*)d_in[2];
    const float* E    = (const float*)d_in[3];
    const float* R    = (const float*)d_in[4];
    const float* bn0g = (const float*)d_in[5];
    const float* bn0b = (const float*)d_in[6];
    const float* bn0m = (const float*)d_in[7];
    const float* bn0v = (const float*)d_in[8];
    const float* fc1w = (const float*)d_in[9];
    const float* fc1b = (const float*)d_in[10];
    const float* bn1g = (const float*)d_in[11];
    const float* bn1b = (const float*)d_in[12];
    const float* bn1m = (const float*)d_in[13];
    const float* bn1v = (const float*)d_in[14];
    const float* fcw  = (const float*)d_in[15];
    const float* fcb  = (const float*)d_in[16];
    const float* bn2g = (const float*)d_in[17];
    const float* bn2b = (const float*)d_in[18];
    const float* bn2m = (const float*)d_in[19];
    const float* bn2v = (const float*)d_in[20];
    const float* fc2w = (const float*)d_in[21];
    const float* fc2b = (const float*)d_in[22];
    const float* bias = (const float*)d_in[23];
    float* out = (float*)d_out;

    k_prep<<<1, 512>>>(fc2w, fc2b, bn2g, bn2b, bn2m, bn2v, fcb,
                       bn0g, bn0b, bn0m, bn0v, bias);
    k_weff_trans<<<329, 256>>>(fcw, fc1w);
    k_reduce<<<49, 256>>>(bn1g, bn1b, bn1m, bn1v);
    k_ctot<<<1, 64>>>();
    k_fused<<<dim3(9, 128), 64>>>(ridx, e1, e2, R, E, fc1b);
    k_out<<<16, 256>>>(out);
}

// round 4
// speedup vs baseline: 2.9144x; 1.8287x over previous
#include <cuda_runtime.h>
#include <math.h>

// ---------------- problem constants ----------------
#define B_N   4096
#define D1    200
#define WIN   400
#define WOUT  392
#define OC    32
#define FW    9
#define T_N   288
#define FCL   12544
#define EPSf  1e-5f

#define NGROUP 8
#define MPERG  50
#define NREL   500
#define RPAD   512
#define GSTR   416     // 13*32 padded G row stride (cols 400..415 are exactly 0)

// ---------------- scratch (__device__ globals) ----------------
__device__ float g_consts[8];              // [0]=CbCz+fc2_b, [1]=a0, [2]=c0, [4]=bias
__device__ float g_wEffP[NGROUP][FCL];
__device__ float g_wEffS[FCL];             // s1[o] * wEff
__device__ float g_ckp[49];                // Ck per-block partials
__device__ float g_W1T[D1 * T_N];          // fc1_w transposed [d][t]
__device__ float g_ktab[RPAD * T_N];       // per-relation conv filters (+bias)
__device__ float g_G[RPAD * GSTR];         // per-relation score vectors
__device__ float g_srp[13][RPAD];          // G row-sum partials per col-block

// ---------------- K2: wEff partials + fc1_w transpose ----------------
__global__ __launch_bounds__(256) void k_weff_trans(const float* __restrict__ fc_w,
                                                    const float* __restrict__ fc1_w,
                                                    const float* __restrict__ bn2_g,
                                                    const float* __restrict__ bn2_v,
                                                    const float* __restrict__ fc2_w)
{
    int bid = blockIdx.x, tid = threadIdx.x;
    if (bid < 104) {
        int g = bid / 13, fb = bid % 13;
        __shared__ float vs[MPERG];
        if (tid < MPERG) {
            int m = g * MPERG + tid;
            float s2 = bn2_g[m] * rsqrtf(bn2_v[m] + EPSf);
            vs[tid] = fc2_w[m] * s2;
        }
        __syncthreads();
        int f4 = fb * 256 + tid;
        if (f4 >= FCL / 4) return;
        const float4* src = reinterpret_cast<const float4*>(fc_w)
                          + (size_t)g * MPERG * (FCL / 4) + f4;
        float4 acc = make_float4(0.f, 0.f, 0.f, 0.f);
#pragma unroll 5
        for (int m = 0; m < MPERG; m++) {
            float vm = vs[m];
            float4 w = src[(size_t)m * (FCL / 4)];
            acc.x = fmaf(vm, w.x, acc.x);
            acc.y = fmaf(vm, w.y, acc.y);
            acc.z = fmaf(vm, w.z, acc.z);
            acc.w = fmaf(vm, w.w, acc.w);
        }
        *reinterpret_cast<float4*>(&g_wEffP[g][f4 * 4]) = acc;
    } else {
        int idx = (bid - 104) * 256 + tid;
        if (idx < D1 * T_N) {
            int d = idx / T_N, t = idx % T_N;
            g_W1T[idx] = fc1_w[t * D1 + d];
        }
    }
}

// ---------------- K3: reduce -> wEffS + Ck partials; block 0 also computes consts ----------
__global__ __launch_bounds__(256) void k_reduce(const float* __restrict__ bn1_g,
                                                const float* __restrict__ bn1_b,
                                                const float* __restrict__ bn1_m,
                                                const float* __restrict__ bn1_v,
                                                const float* __restrict__ bn0_g,
                                                const float* __restrict__ bn0_b,
                                                const float* __restrict__ bn0_m,
                                                const float* __restrict__ bn0_v,
                                                const float* __restrict__ bn2_g,
                                                const float* __restrict__ bn2_b,
                                                const float* __restrict__ bn2_m,
                                                const float* __restrict__ bn2_v,
                                                const float* __restrict__ fc2_w,
                                                const float* __restrict__ fc2_b,
                                                const float* __restrict__ fc_b,
                                                const float* __restrict__ bias)
{
    __shared__ float red[256];
    int tid = threadIdx.x;
    int f = blockIdx.x * 256 + tid;
    int o = f / WOUT;
    float s1 = bn1_g[o] * rsqrtf(bn1_v[o] + EPSf);
    float t1 = bn1_b[o] - bn1_m[o] * s1;
    float s = 0.f;
#pragma unroll
    for (int g = 0; g < NGROUP; g++) s += g_wEffP[g][f];
    g_wEffS[f] = s1 * s;
    red[tid] = t1 * s;
    __syncthreads();
    for (int st = 128; st > 0; st >>= 1) {
        if (tid < st) red[tid] += red[tid + st];
        __syncthreads();
    }
    if (tid == 0) g_ckp[blockIdx.x] = red[0];

    if (blockIdx.x == 0) {
        __syncthreads();
        float l2;
        {
            int m = tid;
            float s2 = bn2_g[m] * rsqrtf(bn2_v[m] + EPSf);
            l2 = fc2_w[m] * (bn2_b[m] - bn2_m[m] * s2) + fc2_w[m] * s2 * fc_b[m];
        }
        if (tid < 144) {
            int m = tid + 256;
            float s2 = bn2_g[m] * rsqrtf(bn2_v[m] + EPSf);
            l2 += fc2_w[m] * (bn2_b[m] - bn2_m[m] * s2) + fc2_w[m] * s2 * fc_b[m];
        }
        red[tid] = l2;
        __syncthreads();
        for (int st = 128; st > 0; st >>= 1) {
            if (tid < st) red[tid] += red[tid + st];
            __syncthreads();
        }
        if (tid == 0) {
            g_consts[0] = red[0] + fc2_b[0];
            float a0 = bn0_g[0] * rsqrtf(bn0_v[0] + EPSf);
            g_consts[1] = a0;
            g_consts[2] = bn0_b[0] - bn0_m[0] * a0;
            g_consts[4] = bias[0];
        }
    }
}

// ---------------- K4: ktab[512,288] = clamp(R) @ W1T + fc1_b ----------------
// 32x32 tile, 128 threads, 2x4 per thread, k=200 (25 chunks of 8), reg double-buffered
__global__ __launch_bounds__(128) void k_ktab(const float* __restrict__ R,
                                              const float* __restrict__ fc1_b)
{
    __shared__ float Xs[32][9];
    __shared__ float Ws[8][32];
    int tid = threadIdx.x;
    int n0 = blockIdx.x * 32, m0 = blockIdx.y * 32;
    int rg = tid >> 3, cg = tid & 7;
    int xr = tid >> 2, xd = (tid & 3) * 2;
    int wk = tid >> 4, wc = (tid & 15) * 2;

    int rrow = m0 + xr; if (rrow >= NREL) rrow = NREL - 1;
    const float* xsrc = R + (size_t)rrow * D1;

    float rx0, rx1, rw0, rw1;
    {
        float2 v = *reinterpret_cast<const float2*>(xsrc + xd);
        rx0 = v.x; rx1 = v.y;
        float2 w = *reinterpret_cast<const float2*>(g_W1T + (size_t)wk * T_N + n0 + wc);
        rw0 = w.x; rw1 = w.y;
    }
    float acc[2][4] = {};
    for (int c = 0; c < 25; c++) {
        __syncthreads();
        Xs[xr][xd] = rx0; Xs[xr][xd + 1] = rx1;
        Ws[wk][wc] = rw0; Ws[wk][wc + 1] = rw1;
        __syncthreads();
        if (c + 1 < 25) {
            int d0 = (c + 1) * 8;
            float2 v = *reinterpret_cast<const float2*>(xsrc + d0 + xd);
            rx0 = v.x; rx1 = v.y;
            float2 w = *reinterpret_cast<const float2*>(g_W1T + (size_t)(d0 + wk) * T_N + n0 + wc);
            rw0 = w.x; rw1 = w.y;
        }
#pragma unroll
        for (int kk = 0; kk < 8; kk++) {
            float x0 = Xs[rg * 2][kk], x1 = Xs[rg * 2 + 1][kk];
            float4 wv = *reinterpret_cast<const float4*>(&Ws[kk][cg * 4]);
            acc[0][0] = fmaf(x0, wv.x, acc[0][0]);
            acc[0][1] = fmaf(x0, wv.y, acc[0][1]);
            acc[0][2] = fmaf(x0, wv.z, acc[0][2]);
            acc[0][3] = fmaf(x0, wv.w, acc[0][3]);
            acc[1][0] = fmaf(x1, wv.x, acc[1][0]);
            acc[1][1] = fmaf(x1, wv.y, acc[1][1]);
            acc[1][2] = fmaf(x1, wv.z, acc[1][2]);
            acc[1][3] = fmaf(x1, wv.w, acc[1][3]);
        }
    }
    float4 b4 = *reinterpret_cast<const float4*>(fc1_b + n0 + cg * 4);
#pragma unroll
    for (int i = 0; i < 2; i++) {
        float4 o4 = make_float4(acc[i][0] + b4.x, acc[i][1] + b4.y,
                                acc[i][2] + b4.z, acc[i][3] + b4.w);
        *reinterpret_cast<float4*>(g_ktab + (size_t)(m0 + rg * 2 + i) * T_N + n0 + cg * 4) = o4;
    }
}

// ---------------- K5: G[512,416] = ktab @ A^T (A banded from wEffS), + row-sum partials ----
__global__ __launch_bounds__(128) void k_G()
{
    __shared__ float Xs[32][9];
    __shared__ float Ws[8][32];
    int tid = threadIdx.x;
    int n0 = blockIdx.x * 32, m0 = blockIdx.y * 32;
    int rg = tid >> 3, cg = tid & 7;
    int xr = tid >> 2, xd = (tid & 3) * 2;
    int wk = tid >> 4, wc = (tid & 15) * 2;

    const float* xsrc = g_ktab + (size_t)(m0 + xr) * T_N;

    float rx0, rx1, rw0, rw1;
    {
        float2 v = *reinterpret_cast<const float2*>(xsrc + xd);
        rx0 = v.x; rx1 = v.y;
        int t = wk, o = t / FW, j = t % FW;
        int w0 = n0 + wc - j, w1 = w0 + 1;
        rw0 = ((unsigned)w0 < (unsigned)WOUT) ? g_wEffS[o * WOUT + w0] : 0.f;
        rw1 = ((unsigned)w1 < (unsigned)WOUT) ? g_wEffS[o * WOUT + w1] : 0.f;
    }
    float acc[2][4] = {};
    for (int c = 0; c < 36; c++) {
        __syncthreads();
        Xs[xr][xd] = rx0; Xs[xr][xd + 1] = rx1;
        Ws[wk][wc] = rw0; Ws[wk][wc + 1] = rw1;
        __syncthreads();
        if (c + 1 < 36) {
            int t0 = (c + 1) * 8;
            float2 v = *reinterpret_cast<const float2*>(xsrc + t0 + xd);
            rx0 = v.x; rx1 = v.y;
            int t = t0 + wk, o = t / FW, j = t % FW;
            int w0 = n0 + wc - j, w1 = w0 + 1;
            rw0 = ((unsigned)w0 < (unsigned)WOUT) ? g_wEffS[o * WOUT + w0] : 0.f;
            rw1 = ((unsigned)w1 < (unsigned)WOUT) ? g_wEffS[o * WOUT + w1] : 0.f;
        }
#pragma unroll
        for (int kk = 0; kk < 8; kk++) {
            float x0 = Xs[rg * 2][kk], x1 = Xs[rg * 2 + 1][kk];
            float4 wv = *reinterpret_cast<const float4*>(&Ws[kk][cg * 4]);
            acc[0][0] = fmaf(x0, wv.x, acc[0][0]);
            acc[0][1] = fmaf(x0, wv.y, acc[0][1]);
            acc[0][2] = fmaf(x0, wv.z, acc[0][2]);
            acc[0][3] = fmaf(x0, wv.w, acc[0][3]);
            acc[1][0] = fmaf(x1, wv.x, acc[1][0]);
            acc[1][1] = fmaf(x1, wv.y, acc[1][1]);
            acc[1][2] = fmaf(x1, wv.z, acc[1][2]);
            acc[1][3] = fmaf(x1, wv.w, acc[1][3]);
        }
    }
    float pr[2];
#pragma unroll
    for (int i = 0; i < 2; i++) {
        *reinterpret_cast<float4*>(g_G + (size_t)(m0 + rg * 2 + i) * GSTR + n0 + cg * 4) =
            make_float4(acc[i][0], acc[i][1], acc[i][2], acc[i][3]);
        pr[i] = (acc[i][0] + acc[i][1]) + (acc[i][2] + acc[i][3]);
    }
#pragma unroll
    for (int off = 1; off < 8; off <<= 1) {
        pr[0] += __shfl_xor_sync(0xFFFFFFFFu, pr[0], off);
        pr[1] += __shfl_xor_sync(0xFFFFFFFFu, pr[1], off);
    }
    if (cg == 0) {
        g_srp[blockIdx.x][m0 + rg * 2]     = pr[0];
        g_srp[blockIdx.x][m0 + rg * 2 + 1] = pr[1];
    }
}

// ---------------- K7: out[b] = tanh( a0*(E[e1].G1 + E[e2].G2) + c0*SG[r] + Ctot ) + bias ----
__global__ __launch_bounds__(256) void k_final(const int* __restrict__ e1_idx,
                                               const int* __restrict__ r_idx,
                                               const int* __restrict__ e2_idx,
                                               const float* __restrict__ E,
                                               float* __restrict__ out)
{
    int b = blockIdx.x * 8 + (threadIdx.x >> 5);
    int l = threadIdx.x & 31;
    int r = r_idx[b], i1 = e1_idx[b], i2 = e2_idx[b];
    const float4* E1 = reinterpret_cast<const float4*>(E + (size_t)i1 * D1);
    const float4* E2 = reinterpret_cast<const float4*>(E + (size_t)i2 * D1);
    const float4* G1 = reinterpret_cast<const float4*>(g_G + (size_t)r * GSTR);
    const float4* G2 = reinterpret_cast<const float4*>(g_G + (size_t)r * GSTR + 200);
    float a0 = g_consts[1], c0 = g_consts[2];

    float dot = 0.f;
    {
        float4 e = E1[l], g = G1[l];
        dot = fmaf(e.x, g.x, fmaf(e.y, g.y, fmaf(e.z, g.z, fmaf(e.w, g.w, dot))));
        e = E2[l]; g = G2[l];
        dot = fmaf(e.x, g.x, fmaf(e.y, g.y, fmaf(e.z, g.z, fmaf(e.w, g.w, dot))));
        if (l < 18) {
            e = E1[32 + l]; g = G1[32 + l];
            dot = fmaf(e.x, g.x, fmaf(e.y, g.y, fmaf(e.z, g.z, fmaf(e.w, g.w, dot))));
            e = E2[32 + l]; g = G2[32 + l];
            dot = fmaf(e.x, g.x, fmaf(e.y, g.y, fmaf(e.z, g.z, fmaf(e.w, g.w, dot))));
        }
    }
    float v = a0 * dot;
    v += g_ckp[l];
    if (l < 17) v += g_ckp[l + 32];
    if (l < 13) v = fmaf(c0, g_srp[l][r], v);
    if (l == 0) v += g_consts[0];
#pragma unroll
    for (int off = 16; off > 0; off >>= 1)
        v += __shfl_xor_sync(0xFFFFFFFFu, v, off);
    if (l == 0) out[b] = tanhf(v) + g_consts[4];
}

// ---------------- launch ----------------
extern "C" void kernel_launch(void* const* d_in, const int* in_sizes, int n_in,
                              void* d_out, int out_size)
{
    const int*   e1   = (const int*)d_in[0];
    const int*   ridx = (const int*)d_in[1];
    const int*   e2   = (const int*)d_in[2];
    const float* E    = (const float*)d_in[3];
    const float* R    = (const float*)d_in[4];
    const float* bn0g = (const float*)d_in[5];
    const float* bn0b = (const float*)d_in[6];
    const float* bn0m = (const float*)d_in[7];
    const float* bn0v = (const float*)d_in[8];
    const float* fc1w = (const float*)d_in[9];
    const float* fc1b = (const float*)d_in[10];
    const float* bn1g = (const float*)d_in[11];
    const float* bn1b = (const float*)d_in[12];
    const float* bn1m = (const float*)d_in[13];
    const float* bn1v = (const float*)d_in[14];
    const float* fcw  = (const float*)d_in[15];
    const float* fcb  = (const float*)d_in[16];
    const float* bn2g = (const float*)d_in[17];
    const float* bn2b = (const float*)d_in[18];
    const float* bn2m = (const float*)d_in[19];
    const float* bn2v = (const float*)d_in[20];
    const float* fc2w = (const float*)d_in[21];
    const float* fc2b = (const float*)d_in[22];
    const float* bias = (const float*)d_in[23];
    float* out = (float*)d_out;

    k_weff_trans<<<329, 256>>>(fcw, fc1w, bn2g, bn2v, fc2w);
    k_reduce<<<49, 256>>>(bn1g, bn1b, bn1m, bn1v,
                          bn0g, bn0b, bn0m, bn0v,
                          bn2g, bn2b, bn2m, bn2v,
                          fc2w, fc2b, fcb, bias);
    k_ktab<<<dim3(9, 16), 128>>>(R, fc1b);
    k_G<<<dim3(13, 16), 128>>>();
    k_final<<<B_N / 8, 256>>>(e1, ridx, e2, E, out);
}

// round 6
// speedup vs baseline: 3.5801x; 1.2284x over previous
#include <cuda_runtime.h>
#include <math.h>

// ---------------- problem constants ----------------
#define B_N   4096
#define D1    200
#define WIN   400
#define WOUT  392
#define OC    32
#define FW    9
#define T_N   288
#define FCL   12544
#define EPSf  1e-5f

#define NGROUP 8
#define MPERG  50
#define NREL   500
#define RPAD   512
#define GSTR   416     // padded G row stride (cols 400..415 are exactly 0)
#define WB     104     // w'-columns per k_G block (4 blocks cover 416)

// ---------------- scratch (__device__ globals) ----------------
__device__ float g_consts[8];              // [0]=CbCz+fc2_b, [1]=a0, [2]=c0, [4]=bias
__device__ float g_wEffP[NGROUP][FCL];
__device__ float g_wEffS[FCL];             // s1[o] * wEff
__device__ float g_ckp[49];                // Ck per-block partials
__device__ float g_W1T[D1 * T_N];          // fc1_w transposed [d][t]
__device__ float g_ktab[RPAD * T_N];       // per-relation conv filters (+bias)
__device__ float g_G[RPAD * GSTR];         // per-relation score vectors
__device__ float g_srp[4][RPAD];           // G row-sum partials per w'-block

// ---------------- K2: wEff partials + fc1_w transpose ----------------
__global__ __launch_bounds__(256) void k_weff_trans(const float* __restrict__ fc_w,
                                                    const float* __restrict__ fc1_w,
                                                    const float* __restrict__ bn2_g,
                                                    const float* __restrict__ bn2_v,
                                                    const float* __restrict__ fc2_w)
{
    int bid = blockIdx.x, tid = threadIdx.x;
    if (bid < 104) {
        int g = bid / 13, fb = bid % 13;
        __shared__ float vs[MPERG];
        if (tid < MPERG) {
            int m = g * MPERG + tid;
            float s2 = bn2_g[m] * rsqrtf(bn2_v[m] + EPSf);
            vs[tid] = fc2_w[m] * s2;
        }
        __syncthreads();
        int f4 = fb * 256 + tid;
        if (f4 >= FCL / 4) return;
        const float4* src = reinterpret_cast<const float4*>(fc_w)
                          + (size_t)g * MPERG * (FCL / 4) + f4;
        float4 acc = make_float4(0.f, 0.f, 0.f, 0.f);
#pragma unroll 5
        for (int m = 0; m < MPERG; m++) {
            float vm = vs[m];
            float4 w = src[(size_t)m * (FCL / 4)];
            acc.x = fmaf(vm, w.x, acc.x);
            acc.y = fmaf(vm, w.y, acc.y);
            acc.z = fmaf(vm, w.z, acc.z);
            acc.w = fmaf(vm, w.w, acc.w);
        }
        *reinterpret_cast<float4*>(&g_wEffP[g][f4 * 4]) = acc;
    } else {
        int idx = (bid - 104) * 256 + tid;
        if (idx < D1 * T_N) {
            int d = idx / T_N, t = idx % T_N;
            g_W1T[idx] = fc1_w[t * D1 + d];
        }
    }
}

// ---------------- K3: reduce -> wEffS + Ck partials; block 0 computes consts ----------------
__global__ __launch_bounds__(256) void k_reduce(const float* __restrict__ bn1_g,
                                                const float* __restrict__ bn1_b,
                                                const float* __restrict__ bn1_m,
                                                const float* __restrict__ bn1_v,
                                                const float* __restrict__ bn0_g,
                                                const float* __restrict__ bn0_b,
                                                const float* __restrict__ bn0_m,
                                                const float* __restrict__ bn0_v,
                                                const float* __restrict__ bn2_g,
                                                const float* __restrict__ bn2_b,
                                                const float* __restrict__ bn2_m,
                                                const float* __restrict__ bn2_v,
                                                const float* __restrict__ fc2_w,
                                                const float* __restrict__ fc2_b,
                                                const float* __restrict__ fc_b,
                                                const float* __restrict__ bias)
{
    __shared__ float red[256];
    int tid = threadIdx.x;
    int f = blockIdx.x * 256 + tid;
    int o = f / WOUT;
    float s1 = bn1_g[o] * rsqrtf(bn1_v[o] + EPSf);
    float t1 = bn1_b[o] - bn1_m[o] * s1;
    float s = 0.f;
#pragma unroll
    for (int g = 0; g < NGROUP; g++) s += g_wEffP[g][f];
    g_wEffS[f] = s1 * s;
    red[tid] = t1 * s;
    __syncthreads();
    for (int st = 128; st > 0; st >>= 1) {
        if (tid < st) red[tid] += red[tid + st];
        __syncthreads();
    }
    if (tid == 0) g_ckp[blockIdx.x] = red[0];

    if (blockIdx.x == 0) {
        __syncthreads();
        float l2;
        {
            int m = tid;
            float s2 = bn2_g[m] * rsqrtf(bn2_v[m] + EPSf);
            l2 = fc2_w[m] * (bn2_b[m] - bn2_m[m] * s2) + fc2_w[m] * s2 * fc_b[m];
        }
        if (tid < 144) {
            int m = tid + 256;
            float s2 = bn2_g[m] * rsqrtf(bn2_v[m] + EPSf);
            l2 += fc2_w[m] * (bn2_b[m] - bn2_m[m] * s2) + fc2_w[m] * s2 * fc_b[m];
        }
        red[tid] = l2;
        __syncthreads();
        for (int st = 128; st > 0; st >>= 1) {
            if (tid < st) red[tid] += red[tid + st];
            __syncthreads();
        }
        if (tid == 0) {
            g_consts[0] = red[0] + fc2_b[0];
            float a0 = bn0_g[0] * rsqrtf(bn0_v[0] + EPSf);
            g_consts[1] = a0;
            g_consts[2] = bn0_b[0] - bn0_m[0] * a0;
            g_consts[4] = bias[0];
        }
    }
}

// ---------------- K4: ktab[512,288] = clamp(R) @ W1T + fc1_b ----------------
__global__ __launch_bounds__(128) void k_ktab(const float* __restrict__ R,
                                              const float* __restrict__ fc1_b)
{
    __shared__ float Xs[32][9];
    __shared__ float Ws[8][32];
    int tid = threadIdx.x;
    int n0 = blockIdx.x * 32, m0 = blockIdx.y * 32;
    int rg = tid >> 3, cg = tid & 7;
    int xr = tid >> 2, xd = (tid & 3) * 2;
    int wk = tid >> 4, wc = (tid & 15) * 2;

    int rrow = m0 + xr; if (rrow >= NREL) rrow = NREL - 1;
    const float* xsrc = R + (size_t)rrow * D1;

    float rx0, rx1, rw0, rw1;
    {
        float2 v = *reinterpret_cast<const float2*>(xsrc + xd);
        rx0 = v.x; rx1 = v.y;
        float2 w = *reinterpret_cast<const float2*>(g_W1T + (size_t)wk * T_N + n0 + wc);
        rw0 = w.x; rw1 = w.y;
    }
    float acc[2][4] = {};
    for (int c = 0; c < 25; c++) {
        __syncthreads();
        Xs[xr][xd] = rx0; Xs[xr][xd + 1] = rx1;
        Ws[wk][wc] = rw0; Ws[wk][wc + 1] = rw1;
        __syncthreads();
        if (c + 1 < 25) {
            int d0 = (c + 1) * 8;
            float2 v = *reinterpret_cast<const float2*>(xsrc + d0 + xd);
            rx0 = v.x; rx1 = v.y;
            float2 w = *reinterpret_cast<const float2*>(g_W1T + (size_t)(d0 + wk) * T_N + n0 + wc);
            rw0 = w.x; rw1 = w.y;
        }
#pragma unroll
        for (int kk = 0; kk < 8; kk++) {
            float x0 = Xs[rg * 2][kk], x1 = Xs[rg * 2 + 1][kk];
            float4 wv = *reinterpret_cast<const float4*>(&Ws[kk][cg * 4]);
            acc[0][0] = fmaf(x0, wv.x, acc[0][0]);
            acc[0][1] = fmaf(x0, wv.y, acc[0][1]);
            acc[0][2] = fmaf(x0, wv.z, acc[0][2]);
            acc[0][3] = fmaf(x0, wv.w, acc[0][3]);
            acc[1][0] = fmaf(x1, wv.x, acc[1][0]);
            acc[1][1] = fmaf(x1, wv.y, acc[1][1]);
            acc[1][2] = fmaf(x1, wv.z, acc[1][2]);
            acc[1][3] = fmaf(x1, wv.w, acc[1][3]);
        }
    }
    float4 b4 = *reinterpret_cast<const float4*>(fc1_b + n0 + cg * 4);
#pragma unroll
    for (int i = 0; i < 2; i++) {
        float4 o4 = make_float4(acc[i][0] + b4.x, acc[i][1] + b4.y,
                                acc[i][2] + b4.z, acc[i][3] + b4.w);
        *reinterpret_cast<float4*>(g_ktab + (size_t)(m0 + rg * 2 + i) * T_N + n0 + cg * 4) = o4;
    }
}

// ---------------- K5: G = ktab @ A^T via smem-resident band; no syncs in mainloop ------------
// Block: 8 relations (warps) x 104 w'-cols (lanes, 4 each). Grid (4, 64).
__global__ __launch_bounds__(256) void k_G()
{
    __shared__ float band[32][136];    // wEffS window per o: [w0-8, w0+103], padded
    __shared__ float kt[8][288];       // ktab tile for this block's 8 relations

    int tid = threadIdx.x;
    int w0 = blockIdx.x * WB;
    int m0 = blockIdx.y * 8;

    // stage ktab tile (8 rows contiguous)
    {
        const float4* src = reinterpret_cast<const float4*>(g_ktab + (size_t)m0 * T_N);
        float4* dst = reinterpret_cast<float4*>(&kt[0][0]);
#pragma unroll
        for (int f4 = tid; f4 < 576; f4 += 256) dst[f4] = src[f4];
    }
    // stage wEffS band (guarded; 28 float4 per o-row)
    for (int f4 = tid; f4 < 896; f4 += 256) {
        int o = f4 / 28, i4 = (f4 % 28) * 4;
        int gb = w0 - 8 + i4;
        const float* wsrc = g_wEffS + o * WOUT;
        float4 v;
        v.x = ((unsigned)(gb    ) < (unsigned)WOUT) ? wsrc[gb    ] : 0.f;
        v.y = ((unsigned)(gb + 1) < (unsigned)WOUT) ? wsrc[gb + 1] : 0.f;
        v.z = ((unsigned)(gb + 2) < (unsigned)WOUT) ? wsrc[gb + 2] : 0.f;
        v.w = ((unsigned)(gb + 3) < (unsigned)WOUT) ? wsrc[gb + 3] : 0.f;
        *reinterpret_cast<float4*>(&band[o][i4]) = v;
    }
    __syncthreads();

    int warp = tid >> 5, l = tid & 31;
    int base = l * 4;                  // local w' offset; lanes >=26 compute discarded work
    const float* ktr = kt[warp];

    float a0 = 0.f, a1 = 0.f, a2 = 0.f, a3 = 0.f;
#pragma unroll
    for (int o = 0; o < 32; o++) {
        float k9[9];
#pragma unroll
        for (int j = 0; j < 9; j++) k9[j] = ktr[o * FW + j];
        float4 wa = *reinterpret_cast<const float4*>(&band[o][base]);
        float4 wb = *reinterpret_cast<const float4*>(&band[o][base + 4]);
        float4 wc = *reinterpret_cast<const float4*>(&band[o][base + 8]);
        float w12[12] = {wa.x, wa.y, wa.z, wa.w, wb.x, wb.y, wb.z, wb.w,
                         wc.x, wc.y, wc.z, wc.w};
#pragma unroll
        for (int j = 0; j < 9; j++) {
            a0 = fmaf(k9[j], w12[8  - j], a0);
            a1 = fmaf(k9[j], w12[9  - j], a1);
            a2 = fmaf(k9[j], w12[10 - j], a2);
            a3 = fmaf(k9[j], w12[11 - j], a3);
        }
    }

    int r = m0 + warp;
    float sum;
    if (base < WB) {
        *reinterpret_cast<float4*>(g_G + (size_t)r * GSTR + w0 + base) =
            make_float4(a0, a1, a2, a3);
        sum = (a0 + a1) + (a2 + a3);
    } else {
        sum = 0.f;
    }
#pragma unroll
    for (int off = 16; off > 0; off >>= 1)
        sum += __shfl_xor_sync(0xFFFFFFFFu, sum, off);
    if (l == 0) g_srp[blockIdx.x][r] = sum;
}

// ---------------- K6: out[b] = tanh( a0*(E[e1].G1 + E[e2].G2) + c0*SG[r] + Ctot ) + bias ----
__global__ __launch_bounds__(256) void k_final(const int* __restrict__ e1_idx,
                                               const int* __restrict__ r_idx,
                                               const int* __restrict__ e2_idx,
                                               const float* __restrict__ E,
                                               float* __restrict__ out)
{
    int b = blockIdx.x * 8 + (threadIdx.x >> 5);
    int l = threadIdx.x & 31;
    int r = r_idx[b], i1 = e1_idx[b], i2 = e2_idx[b];
    const float4* E1 = reinterpret_cast<const float4*>(E + (size_t)i1 * D1);
    const float4* E2 = reinterpret_cast<const float4*>(E + (size_t)i2 * D1);
    const float4* G1 = reinterpret_cast<const float4*>(g_G + (size_t)r * GSTR);
    const float4* G2 = reinterpret_cast<const float4*>(g_G + (size_t)r * GSTR + 200);
    float a0 = g_consts[1], c0 = g_consts[2];

    float dot = 0.f;
    {
        float4 e = E1[l], g = G1[l];
        dot = fmaf(e.x, g.x, fmaf(e.y, g.y, fmaf(e.z, g.z, fmaf(e.w, g.w, dot))));
        e = E2[l]; g = G2[l];
        dot = fmaf(e.x, g.x, fmaf(e.y, g.y, fmaf(e.z, g.z, fmaf(e.w, g.w, dot))));
        if (l < 18) {
            e = E1[32 + l]; g = G1[32 + l];
            dot = fmaf(e.x, g.x, fmaf(e.y, g.y, fmaf(e.z, g.z, fmaf(e.w, g.w, dot))));
            e = E2[32 + l]; g = G2[32 + l];
            dot = fmaf(e.x, g.x, fmaf(e.y, g.y, fmaf(e.z, g.z, fmaf(e.w, g.w, dot))));
        }
    }
    float v = a0 * dot;
    v += g_ckp[l];
    if (l < 17) v += g_ckp[l + 32];
    if (l < 4) v = fmaf(c0, g_srp[l][r], v);
    if (l == 0) v += g_consts[0];
#pragma unroll
    for (int off = 16; off > 0; off >>= 1)
        v += __shfl_xor_sync(0xFFFFFFFFu, v, off);
    if (l == 0) out[b] = tanhf(v) + g_consts[4];
}

// ---------------- launch ----------------
extern "C" void kernel_launch(void* const* d_in, const int* in_sizes, int n_in,
                              void* d_out, int out_size)
{
    const int*   e1   = (const int*)d_in[0];
    const int*   ridx = (const int*)d_in[1];
    const int*   e2   = (const int*)d_in[2];
    const float* E    = (const float*)d_in[3];
    const float* R    = (const float*)d_in[4];
    const float* bn0g = (const float*)d_in[5];
    const float* bn0b = (const float*)d_in[6];
    const float* bn0m = (const float*)d_in[7];
    const float* bn0v = (const float*)d_in[8];
    const float* fc1w = (const float*)d_in[9];
    const float* fc1b = (const float*)d_in[10];
    const float* bn1g = (const float*)d_in[11];
    const float* bn1b = (const float*)d_in[12];
    const float* bn1m = (const float*)d_in[13];
    const float* bn1v = (const float*)d_in[14];
    const float* fcw  = (const float*)d_in[15];
    const float* fcb  = (const float*)d_in[16];
    const float* bn2g = (const float*)d_in[17];
    const float* bn2b = (const float*)d_in[18];
    const float* bn2m = (const float*)d_in[19];
    const float* bn2v = (const float*)d_in[20];
    const float* fc2w = (const float*)d_in[21];
    const float* fc2b = (const float*)d_in[22];
    const float* bias = (const float*)d_in[23];
    float* out = (float*)d_out;

    k_weff_trans<<<329, 256>>>(fcw, fc1w, bn2g, bn2v, fc2w);
    k_reduce<<<49, 256>>>(bn1g, bn1b, bn1m, bn1v,
                          bn0g, bn0b, bn0m, bn0v,
                          bn2g, bn2b, bn2m, bn2v,
                          fc2w, fc2b, fcb, bias);
    k_ktab<<<dim3(9, 16), 128>>>(R, fc1b);
    k_G<<<dim3(4, 64), 256>>>();
    k_final<<<B_N / 8, 256>>>(e1, ridx, e2, E, out);
}

// round 7
// speedup vs baseline: 4.1460x; 1.1581x over previous
#include <cuda_runtime.h>
#include <math.h>

// ---------------- problem constants ----------------
#define B_N   4096
#define D1    200
#define WIN   400
#define WOUT  392
#define OC    32
#define FW    9
#define T_N   288
#define FCL   12544
#define EPSf  1e-5f

#define NGROUP 8
#define MPERG  50
#define NREL   500
#define RPAD   512
#define GSTR   416     // padded G row stride
#define WB     104     // w'-columns per k_G block-x (4 x-blocks cover 416)

// ---------------- scratch (__device__ globals) ----------------
__device__ float g_consts[8];              // [0]=CbCz+fc2_b, [1]=a0, [2]=c0, [4]=bias
__device__ float g_wEffP[NGROUP][FCL];
__device__ float g_wEffS[FCL];             // s1[o] * wEff
__device__ float g_ckp[49];                // Ck per-block partials
__device__ float g_ktab[RPAD * T_N];       // per-relation conv filters (+bias)
__device__ float g_G[RPAD * GSTR];         // per-relation score vectors
__device__ float g_srp[4][RPAD];           // G row-sum partials per w'-block

// ---------------- K1: wEff partials (blocks 0..103) + ktab GEMM (blocks 104..247) ----------
__global__ __launch_bounds__(256) void k_main(const float* __restrict__ fc_w,
                                              const float* __restrict__ fc1_w,
                                              const float* __restrict__ bn2_g,
                                              const float* __restrict__ bn2_v,
                                              const float* __restrict__ fc2_w,
                                              const float* __restrict__ R,
                                              const float* __restrict__ fc1_b)
{
    int bid = blockIdx.x, tid = threadIdx.x;
    if (bid < 104) {
        // ---- wEff partials: group g sums 50 rows of fc_w weighted by v = fc2_w*s2 ----
        int g = bid / 13, fb = bid % 13;
        __shared__ float vs[MPERG];
        if (tid < MPERG) {
            int m = g * MPERG + tid;
            float s2 = bn2_g[m] * rsqrtf(bn2_v[m] + EPSf);
            vs[tid] = fc2_w[m] * s2;
        }
        __syncthreads();
        int f4 = fb * 256 + tid;
        if (f4 >= FCL / 4) return;
        const float4* src = reinterpret_cast<const float4*>(fc_w)
                          + (size_t)g * MPERG * (FCL / 4) + f4;
        float4 acc = make_float4(0.f, 0.f, 0.f, 0.f);
#pragma unroll 5
        for (int m = 0; m < MPERG; m++) {
            float vm = vs[m];
            float4 w = src[(size_t)m * (FCL / 4)];
            acc.x = fmaf(vm, w.x, acc.x);
            acc.y = fmaf(vm, w.y, acc.y);
            acc.z = fmaf(vm, w.z, acc.z);
            acc.w = fmaf(vm, w.w, acc.w);
        }
        *reinterpret_cast<float4*>(&g_wEffP[g][f4 * 4]) = acc;
    } else {
        // ---- ktab[512,288] = clamp(R) @ fc1_w^T + fc1_b ----
        // 32x32 tile, 256 threads, 2x2 per thread, k=200 (25 chunks of 8)
        __shared__ float Xs[32][9];
        __shared__ float Ws[8][32];
        int n = bid - 104;                 // 0..143
        int n0 = (n % 9) * 32, m0 = (n / 9) * 32;
        int rg = tid >> 4, cg = tid & 15;  // compute: rows rg*2.., cols cg*2..
        int xr = tid >> 3, xk = tid & 7;   // X staging
        int wk = tid >> 5, wc = tid & 31;  // W staging

        int rrow = m0 + xr; if (rrow >= NREL) rrow = NREL - 1;
        const float* xsrc = R + (size_t)rrow * D1;
        const float* wsrc = fc1_w + (size_t)(n0 + wc) * D1;

        float rx = xsrc[xk];
        float rw = wsrc[wk];
        float acc00 = 0.f, acc01 = 0.f, acc10 = 0.f, acc11 = 0.f;
        for (int c = 0; c < 25; c++) {
            __syncthreads();
            Xs[xr][xk] = rx;
            Ws[wk][wc] = rw;
            __syncthreads();
            if (c + 1 < 25) {
                int d0 = (c + 1) * 8;
                rx = xsrc[d0 + xk];
                rw = wsrc[d0 + wk];
            }
#pragma unroll
            for (int kk = 0; kk < 8; kk++) {
                float x0 = Xs[rg * 2][kk], x1 = Xs[rg * 2 + 1][kk];
                float2 w2 = *reinterpret_cast<const float2*>(&Ws[kk][cg * 2]);
                acc00 = fmaf(x0, w2.x, acc00);
                acc01 = fmaf(x0, w2.y, acc01);
                acc10 = fmaf(x1, w2.x, acc10);
                acc11 = fmaf(x1, w2.y, acc11);
            }
        }
        float2 b2 = *reinterpret_cast<const float2*>(fc1_b + n0 + cg * 2);
        *reinterpret_cast<float2*>(g_ktab + (size_t)(m0 + rg * 2) * T_N + n0 + cg * 2) =
            make_float2(acc00 + b2.x, acc01 + b2.y);
        *reinterpret_cast<float2*>(g_ktab + (size_t)(m0 + rg * 2 + 1) * T_N + n0 + cg * 2) =
            make_float2(acc10 + b2.x, acc11 + b2.y);
    }
}

// ---------------- K2: reduce -> wEffS + Ck partials; block 0 computes consts ----------------
__global__ __launch_bounds__(256) void k_reduce(const float* __restrict__ bn1_g,
                                                const float* __restrict__ bn1_b,
                                                const float* __restrict__ bn1_m,
                                                const float* __restrict__ bn1_v,
                                                const float* __restrict__ bn0_g,
                                                const float* __restrict__ bn0_b,
                                                const float* __restrict__ bn0_m,
                                                const float* __restrict__ bn0_v,
                                                const float* __restrict__ bn2_g,
                                                const float* __restrict__ bn2_b,
                                                const float* __restrict__ bn2_m,
                                                const float* __restrict__ bn2_v,
                                                const float* __restrict__ fc2_w,
                                                const float* __restrict__ fc2_b,
                                                const float* __restrict__ fc_b,
                                                const float* __restrict__ bias)
{
    __shared__ float red[256];
    int tid = threadIdx.x;
    int f = blockIdx.x * 256 + tid;
    int o = f / WOUT;
    float s1 = bn1_g[o] * rsqrtf(bn1_v[o] + EPSf);
    float t1 = bn1_b[o] - bn1_m[o] * s1;
    float s = 0.f;
#pragma unroll
    for (int g = 0; g < NGROUP; g++) s += g_wEffP[g][f];
    g_wEffS[f] = s1 * s;
    red[tid] = t1 * s;
    __syncthreads();
    for (int st = 128; st > 0; st >>= 1) {
        if (tid < st) red[tid] += red[tid + st];
        __syncthreads();
    }
    if (tid == 0) g_ckp[blockIdx.x] = red[0];

    if (blockIdx.x == 0) {
        __syncthreads();
        float l2;
        {
            int m = tid;
            float s2 = bn2_g[m] * rsqrtf(bn2_v[m] + EPSf);
            l2 = fc2_w[m] * (bn2_b[m] - bn2_m[m] * s2) + fc2_w[m] * s2 * fc_b[m];
        }
        if (tid < 144) {
            int m = tid + 256;
            float s2 = bn2_g[m] * rsqrtf(bn2_v[m] + EPSf);
            l2 += fc2_w[m] * (bn2_b[m] - bn2_m[m] * s2) + fc2_w[m] * s2 * fc_b[m];
        }
        red[tid] = l2;
        __syncthreads();
        for (int st = 128; st > 0; st >>= 1) {
            if (tid < st) red[tid] += red[tid + st];
            __syncthreads();
        }
        if (tid == 0) {
            g_consts[0] = red[0] + fc2_b[0];
            float a0 = bn0_g[0] * rsqrtf(bn0_v[0] + EPSf);
            g_consts[1] = a0;
            g_consts[2] = bn0_b[0] - bn0_m[0] * a0;
            g_consts[4] = bias[0];
        }
    }
}

// ---------------- K3: G = ktab @ A^T via smem band; 16 relations x 104 cols, 1 wave -------
__global__ __launch_bounds__(512) void k_G()
{
    __shared__ float band[32][136];    // wEffS window per o: [w0-8, w0+103], padded
    __shared__ float kt[16][288];      // ktab tile for this block's 16 relations

    int tid = threadIdx.x;
    int w0 = blockIdx.x * WB;
    int m0 = blockIdx.y * 16;

    // stage ktab tile (16 rows contiguous)
    {
        const float4* src = reinterpret_cast<const float4*>(g_ktab + (size_t)m0 * T_N);
        float4* dst = reinterpret_cast<float4*>(&kt[0][0]);
#pragma unroll
        for (int f4 = tid; f4 < 1152; f4 += 512) dst[f4] = src[f4];
    }
    // stage wEffS band (guarded; 28 float4 per o-row)
    for (int f4 = tid; f4 < 896; f4 += 512) {
        int o = f4 / 28, i4 = (f4 % 28) * 4;
        int gb = w0 - 8 + i4;
        const float* wsrc = g_wEffS + o * WOUT;
        float4 v;
        v.x = ((unsigned)(gb    ) < (unsigned)WOUT) ? wsrc[gb    ] : 0.f;
        v.y = ((unsigned)(gb + 1) < (unsigned)WOUT) ? wsrc[gb + 1] : 0.f;
        v.z = ((unsigned)(gb + 2) < (unsigned)WOUT) ? wsrc[gb + 2] : 0.f;
        v.w = ((unsigned)(gb + 3) < (unsigned)WOUT) ? wsrc[gb + 3] : 0.f;
        *reinterpret_cast<float4*>(&band[o][i4]) = v;
    }
    __syncthreads();

    int warp = tid >> 5, l = tid & 31;
    int base = l * 4;                  // lanes >= 26 compute discarded work
    const float* ktr = kt[warp];

    float a0 = 0.f, a1 = 0.f, a2 = 0.f, a3 = 0.f;
#pragma unroll
    for (int o = 0; o < 32; o++) {
        float k9[9];
#pragma unroll
        for (int j = 0; j < 9; j++) k9[j] = ktr[o * FW + j];
        float4 wa = *reinterpret_cast<const float4*>(&band[o][base]);
        float4 wb = *reinterpret_cast<const float4*>(&band[o][base + 4]);
        float4 wc = *reinterpret_cast<const float4*>(&band[o][base + 8]);
        float w12[12] = {wa.x, wa.y, wa.z, wa.w, wb.x, wb.y, wb.z, wb.w,
                         wc.x, wc.y, wc.z, wc.w};
#pragma unroll
        for (int j = 0; j < 9; j++) {
            a0 = fmaf(k9[j], w12[8  - j], a0);
            a1 = fmaf(k9[j], w12[9  - j], a1);
            a2 = fmaf(k9[j], w12[10 - j], a2);
            a3 = fmaf(k9[j], w12[11 - j], a3);
        }
    }

    int r = m0 + warp;
    float sum;
    if (base < WB) {
        *reinterpret_cast<float4*>(g_G + (size_t)r * GSTR + w0 + base) =
            make_float4(a0, a1, a2, a3);
        sum = (a0 + a1) + (a2 + a3);
    } else {
        sum = 0.f;
    }
#pragma unroll
    for (int off = 16; off > 0; off >>= 1)
        sum += __shfl_xor_sync(0xFFFFFFFFu, sum, off);
    if (l == 0) g_srp[blockIdx.x][r] = sum;
}

// ---------------- K4: out[b] = tanh( a0*(E[e1].G1 + E[e2].G2) + c0*SG[r] + Ctot ) + bias ----
__global__ __launch_bounds__(256) void k_final(const int* __restrict__ e1_idx,
                                               const int* __restrict__ r_idx,
                                               const int* __restrict__ e2_idx,
                                               const float* __restrict__ E,
                                               float* __restrict__ out)
{
    int b = blockIdx.x * 8 + (threadIdx.x >> 5);
    int l = threadIdx.x & 31;
    int r = r_idx[b], i1 = e1_idx[b], i2 = e2_idx[b];
    const float4* E1 = reinterpret_cast<const float4*>(E + (size_t)i1 * D1);
    const float4* E2 = reinterpret_cast<const float4*>(E + (size_t)i2 * D1);
    const float4* G1 = reinterpret_cast<const float4*>(g_G + (size_t)r * GSTR);
    const float4* G2 = reinterpret_cast<const float4*>(g_G + (size_t)r * GSTR + 200);
    float a0 = g_consts[1], c0 = g_consts[2];

    float dot = 0.f;
    {
        float4 e = E1[l], g = G1[l];
        dot = fmaf(e.x, g.x, fmaf(e.y, g.y, fmaf(e.z, g.z, fmaf(e.w, g.w, dot))));
        e = E2[l]; g = G2[l];
        dot = fmaf(e.x, g.x, fmaf(e.y, g.y, fmaf(e.z, g.z, fmaf(e.w, g.w, dot))));
        if (l < 18) {
            e = E1[32 + l]; g = G1[32 + l];
            dot = fmaf(e.x, g.x, fmaf(e.y, g.y, fmaf(e.z, g.z, fmaf(e.w, g.w, dot))));
            e = E2[32 + l]; g = G2[32 + l];
            dot = fmaf(e.x, g.x, fmaf(e.y, g.y, fmaf(e.z, g.z, fmaf(e.w, g.w, dot))));
        }
    }
    float v = a0 * dot;
    v += g_ckp[l];
    if (l < 17) v += g_ckp[l + 32];
    if (l < 4) v = fmaf(c0, g_srp[l][r], v);
    if (l == 0) v += g_consts[0];
#pragma unroll
    for (int off = 16; off > 0; off >>= 1)
        v += __shfl_xor_sync(0xFFFFFFFFu, v, off);
    if (l == 0) out[b] = tanhf(v) + g_consts[4];
}

// ---------------- launch ----------------
extern "C" void kernel_launch(void* const* d_in, const int* in_sizes, int n_in,
                              void* d_out, int out_size)
{
    const int*   e1   = (const int*)d_in[0];
    const int*   ridx = (const int*)d_in[1];
    const int*   e2   = (const int*)d_in[2];
    const float* E    = (const float*)d_in[3];
    const float* R    = (const float*)d_in[4];
    const float* bn0g = (const float*)d_in[5];
    const float* bn0b = (const float*)d_in[6];
    const float* bn0m = (const float*)d_in[7];
    const float* bn0v = (const float*)d_in[8];
    const float* fc1w = (const float*)d_in[9];
    const float* fc1b = (const float*)d_in[10];
    const float* bn1g = (const float*)d_in[11];
    const float* bn1b = (const float*)d_in[12];
    const float* bn1m = (const float*)d_in[13];
    const float* bn1v = (const float*)d_in[14];
    const float* fcw  = (const float*)d_in[15];
    const float* fcb  = (const float*)d_in[16];
    const float* bn2g = (const float*)d_in[17];
    const float* bn2b = (const float*)d_in[18];
    const float* bn2m = (const float*)d_in[19];
    const float* bn2v = (const float*)d_in[20];
    const float* fc2w = (const float*)d_in[21];
    const float* fc2b = (const float*)d_in[22];
    const float* bias = (const float*)d_in[23];
    float* out = (float*)d_out;

    k_main<<<248, 256>>>(fcw, fc1w, bn2g, bn2v, fc2w, R, fc1b);
    k_reduce<<<49, 256>>>(bn1g, bn1b, bn1m, bn1v,
                          bn0g, bn0b, bn0m, bn0v,
                          bn2g, bn2b, bn2m, bn2v,
                          fc2w, fc2b, fcb, bias);
    k_G<<<dim3(4, 32), 512>>>();
    k_final<<<B_N / 8, 256>>>(e1, ridx, e2, E, out);
}

// round 8
// speedup vs baseline: 4.1967x; 1.0122x over previous
#include <cuda_runtime.h>
#include <math.h>

// ---------------- problem constants ----------------
#define B_N   4096
#define D1    200
#define WIN   400
#define WOUT  392
#define OC    32
#define FW    9
#define T_N   288
#define FCL   12544
#define EPSf  1e-5f

#define NGROUP 8
#define MPERG  50
#define NREL   500
#define RPAD   512
#define GSTR   416     // padded G row stride
#define WB     104     // w'-columns per k_G block-x (4 x-blocks cover 416)

// ---------------- scratch (__device__ globals) ----------------
__device__ float g_consts[8];              // [0]=CbCz+fc2_b, [1]=a0, [2]=c0, [3]=Ctot, [4]=bias
__device__ float g_wEffP[NGROUP][FCL];
__device__ float g_wEffS[FCL];             // s1[o] * wEff
__device__ float g_ckp[49];                // Ck per-block partials
__device__ float g_ktab[RPAD * T_N];       // per-relation conv filters (+bias)
__device__ float g_G[RPAD * GSTR];         // per-relation score vectors
__device__ float g_srp[4][RPAD];           // G row-sum partials per w'-block

// ---------------- K1: wEff partials (blocks 0..103) + ktab GEMM (blocks 104..247) ----------
__global__ __launch_bounds__(256) void k_main(const float* __restrict__ fc_w,
                                              const float* __restrict__ fc1_w,
                                              const float* __restrict__ bn2_g,
                                              const float* __restrict__ bn2_v,
                                              const float* __restrict__ fc2_w,
                                              const float* __restrict__ R,
                                              const float* __restrict__ fc1_b)
{
    int bid = blockIdx.x, tid = threadIdx.x;
    if (bid < 104) {
        int g = bid / 13, fb = bid % 13;
        __shared__ float vs[MPERG];
        if (tid < MPERG) {
            int m = g * MPERG + tid;
            float s2 = bn2_g[m] * rsqrtf(bn2_v[m] + EPSf);
            vs[tid] = fc2_w[m] * s2;
        }
        __syncthreads();
        int f4 = fb * 256 + tid;
        if (f4 >= FCL / 4) return;
        const float4* src = reinterpret_cast<const float4*>(fc_w)
                          + (size_t)g * MPERG * (FCL / 4) + f4;
        float4 acc = make_float4(0.f, 0.f, 0.f, 0.f);
#pragma unroll 5
        for (int m = 0; m < MPERG; m++) {
            float vm = vs[m];
            float4 w = src[(size_t)m * (FCL / 4)];
            acc.x = fmaf(vm, w.x, acc.x);
            acc.y = fmaf(vm, w.y, acc.y);
            acc.z = fmaf(vm, w.z, acc.z);
            acc.w = fmaf(vm, w.w, acc.w);
        }
        *reinterpret_cast<float4*>(&g_wEffP[g][f4 * 4]) = acc;
    } else {
        // ---- ktab[512,288] = clamp(R) @ fc1_w^T + fc1_b ----
        __shared__ float Xs[32][9];
        __shared__ float Ws[8][32];
        int n = bid - 104;
        int n0 = (n % 9) * 32, m0 = (n / 9) * 32;
        int rg = tid >> 4, cg = tid & 15;
        int xr = tid >> 3, xk = tid & 7;
        int wk = tid >> 5, wc = tid & 31;

        int rrow = m0 + xr; if (rrow >= NREL) rrow = NREL - 1;
        const float* xsrc = R + (size_t)rrow * D1;
        const float* wsrc = fc1_w + (size_t)(n0 + wc) * D1;

        float rx = xsrc[xk];
        float rw = wsrc[wk];
        float acc00 = 0.f, acc01 = 0.f, acc10 = 0.f, acc11 = 0.f;
        for (int c = 0; c < 25; c++) {
            __syncthreads();
            Xs[xr][xk] = rx;
            Ws[wk][wc] = rw;
            __syncthreads();
            if (c + 1 < 25) {
                int d0 = (c + 1) * 8;
                rx = xsrc[d0 + xk];
                rw = wsrc[d0 + wk];
            }
#pragma unroll
            for (int kk = 0; kk < 8; kk++) {
                float x0 = Xs[rg * 2][kk], x1 = Xs[rg * 2 + 1][kk];
                float2 w2 = *reinterpret_cast<const float2*>(&Ws[kk][cg * 2]);
                acc00 = fmaf(x0, w2.x, acc00);
                acc01 = fmaf(x0, w2.y, acc01);
                acc10 = fmaf(x1, w2.x, acc10);
                acc11 = fmaf(x1, w2.y, acc11);
            }
        }
        float2 b2 = *reinterpret_cast<const float2*>(fc1_b + n0 + cg * 2);
        *reinterpret_cast<float2*>(g_ktab + (size_t)(m0 + rg * 2) * T_N + n0 + cg * 2) =
            make_float2(acc00 + b2.x, acc01 + b2.y);
        *reinterpret_cast<float2*>(g_ktab + (size_t)(m0 + rg * 2 + 1) * T_N + n0 + cg * 2) =
            make_float2(acc10 + b2.x, acc11 + b2.y);
    }
}

// ---------------- K2: reduce -> wEffS + Ck partials; block 0 computes consts ----------------
__global__ __launch_bounds__(256) void k_reduce(const float* __restrict__ bn1_g,
                                                const float* __restrict__ bn1_b,
                                                const float* __restrict__ bn1_m,
                                                const float* __restrict__ bn1_v,
                                                const float* __restrict__ bn0_g,
                                                const float* __restrict__ bn0_b,
                                                const float* __restrict__ bn0_m,
                                                const float* __restrict__ bn0_v,
                                                const float* __restrict__ bn2_g,
                                                const float* __restrict__ bn2_b,
                                                const float* __restrict__ bn2_m,
                                                const float* __restrict__ bn2_v,
                                                const float* __restrict__ fc2_w,
                                                const float* __restrict__ fc2_b,
                                                const float* __restrict__ fc_b,
                                                const float* __restrict__ bias)
{
    __shared__ float red[256];
    int tid = threadIdx.x;
    int f = blockIdx.x * 256 + tid;
    int o = f / WOUT;
    float s1 = bn1_g[o] * rsqrtf(bn1_v[o] + EPSf);
    float t1 = bn1_b[o] - bn1_m[o] * s1;
    float s = 0.f;
#pragma unroll
    for (int g = 0; g < NGROUP; g++) s += g_wEffP[g][f];
    g_wEffS[f] = s1 * s;
    red[tid] = t1 * s;
    __syncthreads();
    for (int st = 128; st > 0; st >>= 1) {
        if (tid < st) red[tid] += red[tid + st];
        __syncthreads();
    }
    if (tid == 0) g_ckp[blockIdx.x] = red[0];

    if (blockIdx.x == 0) {
        __syncthreads();
        float l2;
        {
            int m = tid;
            float s2 = bn2_g[m] * rsqrtf(bn2_v[m] + EPSf);
            l2 = fc2_w[m] * (bn2_b[m] - bn2_m[m] * s2) + fc2_w[m] * s2 * fc_b[m];
        }
        if (tid < 144) {
            int m = tid + 256;
            float s2 = bn2_g[m] * rsqrtf(bn2_v[m] + EPSf);
            l2 += fc2_w[m] * (bn2_b[m] - bn2_m[m] * s2) + fc2_w[m] * s2 * fc_b[m];
        }
        red[tid] = l2;
        __syncthreads();
        for (int st = 128; st > 0; st >>= 1) {
            if (tid < st) red[tid] += red[tid + st];
            __syncthreads();
        }
        if (tid == 0) {
            g_consts[0] = red[0] + fc2_b[0];
            float a0 = bn0_g[0] * rsqrtf(bn0_v[0] + EPSf);
            g_consts[1] = a0;
            g_consts[2] = bn0_b[0] - bn0_m[0] * a0;
            g_consts[4] = bias[0];
        }
    }
}

// ---------------- K3: G = ktab @ A^T via smem band; plus Ctot in extra block row ------------
__global__ __launch_bounds__(512) void k_G()
{
    // extra block row (y == 32): block (0,32) reduces Ctot; others exit
    if (blockIdx.y == 32) {
        if (blockIdx.x != 0 || threadIdx.x >= 32) return;
        int l = threadIdx.x;
        float v = (l < 49) ? g_ckp[l] : 0.f;
        if (l < 17) v += g_ckp[l + 32];
#pragma unroll
        for (int off = 16; off > 0; off >>= 1)
            v += __shfl_xor_sync(0xFFFFFFFFu, v, off);
        if (l == 0) g_consts[3] = v + g_consts[0];
        return;
    }

    __shared__ float band[32][136];
    __shared__ float kt[16][288];

    int tid = threadIdx.x;
    int w0 = blockIdx.x * WB;
    int m0 = blockIdx.y * 16;

    {
        const float4* src = reinterpret_cast<const float4*>(g_ktab + (size_t)m0 * T_N);
        float4* dst = reinterpret_cast<float4*>(&kt[0][0]);
#pragma unroll
        for (int f4 = tid; f4 < 1152; f4 += 512) dst[f4] = src[f4];
    }
    for (int f4 = tid; f4 < 896; f4 += 512) {
        int o = f4 / 28, i4 = (f4 % 28) * 4;
        int gb = w0 - 8 + i4;
        const float* wsrc = g_wEffS + o * WOUT;
        float4 v;
        v.x = ((unsigned)(gb    ) < (unsigned)WOUT) ? wsrc[gb    ] : 0.f;
        v.y = ((unsigned)(gb + 1) < (unsigned)WOUT) ? wsrc[gb + 1] : 0.f;
        v.z = ((unsigned)(gb + 2) < (unsigned)WOUT) ? wsrc[gb + 2] : 0.f;
        v.w = ((unsigned)(gb + 3) < (unsigned)WOUT) ? wsrc[gb + 3] : 0.f;
        *reinterpret_cast<float4*>(&band[o][i4]) = v;
    }
    __syncthreads();

    int warp = tid >> 5, l = tid & 31;
    int base = l * 4;
    const float* ktr = kt[warp];

    float a0 = 0.f, a1 = 0.f, a2 = 0.f, a3 = 0.f;
#pragma unroll
    for (int o = 0; o < 32; o++) {
        float k9[9];
#pragma unroll
        for (int j = 0; j < 9; j++) k9[j] = ktr[o * FW + j];
        float4 wa = *reinterpret_cast<const float4*>(&band[o][base]);
        float4 wb = *reinterpret_cast<const float4*>(&band[o][base + 4]);
        float4 wc = *reinterpret_cast<const float4*>(&band[o][base + 8]);
        float w12[12] = {wa.x, wa.y, wa.z, wa.w, wb.x, wb.y, wb.z, wb.w,
                         wc.x, wc.y, wc.z, wc.w};
#pragma unroll
        for (int j = 0; j < 9; j++) {
            a0 = fmaf(k9[j], w12[8  - j], a0);
            a1 = fmaf(k9[j], w12[9  - j], a1);
            a2 = fmaf(k9[j], w12[10 - j], a2);
            a3 = fmaf(k9[j], w12[11 - j], a3);
        }
    }

    int r = m0 + warp;
    float sum;
    if (base < WB) {
        *reinterpret_cast<float4*>(g_G + (size_t)r * GSTR + w0 + base) =
            make_float4(a0, a1, a2, a3);
        sum = (a0 + a1) + (a2 + a3);
    } else {
        sum = 0.f;
    }
#pragma unroll
    for (int off = 16; off > 0; off >>= 1)
        sum += __shfl_xor_sync(0xFFFFFFFFu, sum, off);
    if (l == 0) g_srp[blockIdx.x][r] = sum;
}

// ---------------- K4: out[b] = tanh( a0*dot + c0*SG[r] + Ctot ) + bias ---------------------
// Batched loads: lanes 0..24 own exactly 2 float4 per 50-float4 row; all 8 LDG.128 issued
// up-front (independent) so only one DRAM round-trip is exposed. Lanes 25..29 fetch the
// scalar terms in parallel.
__global__ __launch_bounds__(256) void k_final(const int* __restrict__ e1_idx,
                                               const int* __restrict__ r_idx,
                                               const int* __restrict__ e2_idx,
                                               const float* __restrict__ E,
                                               float* __restrict__ out)
{
    int b = blockIdx.x * 8 + (threadIdx.x >> 5);
    int l = threadIdx.x & 31;
    int r = r_idx[b], i1 = e1_idx[b], i2 = e2_idx[b];
    float a0 = g_consts[1], c0 = g_consts[2];

    float v;
    if (l < 25) {
        const float4* E1 = reinterpret_cast<const float4*>(E + (size_t)i1 * D1);
        const float4* E2 = reinterpret_cast<const float4*>(E + (size_t)i2 * D1);
        const float4* Gp = reinterpret_cast<const float4*>(g_G + (size_t)r * GSTR);
        float4 ea0 = E1[l], ea1 = E1[l + 25];
        float4 eb0 = E2[l], eb1 = E2[l + 25];
        float4 ga0 = Gp[l], ga1 = Gp[l + 25];
        float4 gb0 = Gp[l + 50], gb1 = Gp[l + 75];
        float d0 = fmaf(ea0.x, ga0.x, fmaf(ea0.y, ga0.y, fmaf(ea0.z, ga0.z, ea0.w * ga0.w)));
        float d1 = fmaf(ea1.x, ga1.x, fmaf(ea1.y, ga1.y, fmaf(ea1.z, ga1.z, ea1.w * ga1.w)));
        float d2 = fmaf(eb0.x, gb0.x, fmaf(eb0.y, gb0.y, fmaf(eb0.z, gb0.z, eb0.w * gb0.w)));
        float d3 = fmaf(eb1.x, gb1.x, fmaf(eb1.y, gb1.y, fmaf(eb1.z, gb1.z, eb1.w * gb1.w)));
        v = a0 * ((d0 + d1) + (d2 + d3));
    } else if (l < 29) {
        v = c0 * g_srp[l - 25][r];
    } else if (l == 29) {
        v = g_consts[3];
    } else {
        v = 0.f;
    }
#pragma unroll
    for (int off = 16; off > 0; off >>= 1)
        v += __shfl_xor_sync(0xFFFFFFFFu, v, off);
    if (l == 0) out[b] = tanhf(v) + g_consts[4];
}

// ---------------- launch ----------------
extern "C" void kernel_launch(void* const* d_in, const int* in_sizes, int n_in,
                              void* d_out, int out_size)
{
    const int*   e1   = (const int*)d_in[0];
    const int*   ridx = (const int*)d_in[1];
    const int*   e2   = (const int*)d_in[2];
    const float* E    = (const float*)d_in[3];
    const float* R    = (const float*)d_in[4];
    const float* bn0g = (const float*)d_in[5];
    const float* bn0b = (const float*)d_in[6];
    const float* bn0m = (const float*)d_in[7];
    const float* bn0v = (const float*)d_in[8];
    const float* fc1w = (const float*)d_in[9];
    const float* fc1b = (const float*)d_in[10];
    const float* bn1g = (const float*)d_in[11];
    const float* bn1b = (const float*)d_in[12];
    const float* bn1m = (const float*)d_in[13];
    const float* bn1v = (const float*)d_in[14];
    const float* fcw  = (const float*)d_in[15];
    const float* fcb  = (const float*)d_in[16];
    const float* bn2g = (const float*)d_in[17];
    const float* bn2b = (const float*)d_in[18];
    const float* bn2m = (const float*)d_in[19];
    const float* bn2v = (const float*)d_in[20];
    const float* fc2w = (const float*)d_in[21];
    const float* fc2b = (const float*)d_in[22];
    const float* bias = (const float*)d_in[23];
    float* out = (float*)d_out;

    k_main<<<248, 256>>>(fcw, fc1w, bn2g, bn2v, fc2w, R, fc1b);
    k_reduce<<<49, 256>>>(bn1g, bn1b, bn1m, bn1v,
                          bn0g, bn0b, bn0m, bn0v,
                          bn2g, bn2b, bn2m, bn2v,
                          fc2w, fc2b, fcb, bias);
    k_G<<<dim3(4, 33), 512>>>();
    k_final<<<B_N / 8, 256>>>(e1, ridx, e2, E, out);
}